// round 4
// baseline (speedup 1.0000x reference)
#include <cuda_runtime.h>
#include <math.h>

#define TPB 128
#define MAX_BLOCKS 4096
#define ANGW 0.1f
#define RAD2DEG 57.29577951308232f
#define PI_F 3.14159265358979f

typedef unsigned long long ull;

__device__ float g_ptr_[MAX_BLOCKS];
__device__ float g_pang[MAX_BLOCKS];
__device__ unsigned int g_count = 0;

// ---------- packed f32x2 primitives (sm_103a) ----------
__device__ __forceinline__ ull f2pk(float lo, float hi) {
    ull r;
    asm("mov.b64 %0, {%1, %2};" : "=l"(r)
        : "r"(__float_as_uint(lo)), "r"(__float_as_uint(hi)));
    return r;
}
__device__ __forceinline__ void f2up(ull v, float& lo, float& hi) {
    unsigned a, b;
    asm("mov.b64 {%0, %1}, %2;" : "=r"(a), "=r"(b) : "l"(v));
    lo = __uint_as_float(a); hi = __uint_as_float(b);
}
__device__ __forceinline__ ull f2mul(ull a, ull b) {
    ull d; asm("mul.rn.f32x2 %0, %1, %2;" : "=l"(d) : "l"(a), "l"(b)); return d;
}
__device__ __forceinline__ ull f2add(ull a, ull b) {
    ull d; asm("add.rn.f32x2 %0, %1, %2;" : "=l"(d) : "l"(a), "l"(b)); return d;
}
__device__ __forceinline__ ull f2fma(ull a, ull b, ull c) {
    ull d; asm("fma.rn.f32x2 %0, %1, %2, %3;" : "=l"(d) : "l"(a), "l"(b), "l"(c)); return d;
}
#define F2NEG(a) ((a) ^ 0x8000000080000000ULL)
__device__ __forceinline__ ull f2sub(ull a, ull b) { return f2add(a, F2NEG(b)); }
__device__ __forceinline__ ull f2c(float c) { return f2pk(c, c); }
// a*b - c*d
__device__ __forceinline__ ull f2cr(ull a, ull b, ull c, ull d) {
    return f2fma(a, b, F2NEG(f2mul(c, d)));
}
__device__ __forceinline__ ull f2rsqrt_clamped(ull x, float floor_) {
    float l, h; f2up(x, l, h);
    return f2pk(rsqrtf(fmaxf(l, floor_)), rsqrtf(fmaxf(h, floor_)));
}

// Fast acos (scalar): Abramowitz-Stegun 4.4.45, max abs err ~6.7e-5 rad.
__device__ __forceinline__ float fast_acos(float x)
{
    float ax = fabsf(x);
    float p = fmaf(ax, -0.0187293f, 0.0742610f);
    p = fmaf(p, ax, -0.2121144f);
    p = fmaf(p, ax, 1.5707288f);
    float s = fmaxf(1.0f - ax, 1e-30f);
    float r = s * rsqrtf(s) * p;
    return (x >= 0.f) ? r : PI_F - r;
}

__device__ __forceinline__ void pick3(
    float n0, float n1, float n2,
    float x0, float y0, float z0,
    float x1, float y1, float z1,
    float x2, float y2, float z2,
    float& vx, float& vy, float& vz)
{
    float bx = x0, by = y0, bz = z0, bn = n0;
    if (n1 > bn) { bx = x1; by = y1; bz = z1; bn = n1; }
    if (n2 > bn) { bx = x2; by = y2; bz = z2; bn = n2; }
    float inv = rsqrtf(fmaxf(bn, 1e-30f));
    vx = bx * inv; vy = by * inv; vz = bz * inv;
}

// Packed eigenvector for eigenvalue lam (both lanes simultaneously).
__device__ __forceinline__ void eigvec2(
    ull a00, ull a01, ull a02, ull a11, ull a12, ull a22,
    ull lam, ull v[3])
{
    ull r0x = f2sub(a00, lam), r1y = f2sub(a11, lam), r2z = f2sub(a22, lam);

    ull c0x = f2cr(a01, a12, a02, r1y);
    ull c0y = f2cr(a02, a01, r0x, a12);
    ull c0z = f2cr(r0x, r1y, a01, a01);
    ull c1x = f2cr(a01, r2z, a02, a12);
    ull c1y = f2cr(a02, a02, r0x, r2z);
    ull c1z = f2cr(r0x, a12, a01, a02);
    ull c2x = f2cr(r1y, r2z, a12, a12);
    ull c2y = f2cr(a12, a02, a01, r2z);
    ull c2z = f2cr(a01, a12, r1y, a02);

    ull n0 = f2fma(c0x, c0x, f2fma(c0y, c0y, f2mul(c0z, c0z)));
    ull n1 = f2fma(c1x, c1x, f2fma(c1y, c1y, f2mul(c1z, c1z)));
    ull n2 = f2fma(c2x, c2x, f2fma(c2y, c2y, f2mul(c2z, c2z)));

    float n0l,n0h,n1l,n1h,n2l,n2h;
    f2up(n0,n0l,n0h); f2up(n1,n1l,n1h); f2up(n2,n2l,n2h);
    float x0l,x0h,y0l,y0h,z0l,z0h;
    float x1l,x1h,y1l,y1h,z1l,z1h;
    float x2l,x2h,y2l,y2h,z2l,z2h;
    f2up(c0x,x0l,x0h); f2up(c0y,y0l,y0h); f2up(c0z,z0l,z0h);
    f2up(c1x,x1l,x1h); f2up(c1y,y1l,y1h); f2up(c1z,z1l,z1h);
    f2up(c2x,x2l,x2h); f2up(c2y,y2l,y2h); f2up(c2z,z2l,z2h);

    float vxl,vyl,vzl, vxh,vyh,vzh;
    pick3(n0l,n1l,n2l, x0l,y0l,z0l, x1l,y1l,z1l, x2l,y2l,z2l, vxl,vyl,vzl);
    pick3(n0h,n1h,n2h, x0h,y0h,z0h, x1h,y1h,z1h, x2h,y2h,z2h, vxh,vyh,vzh);

    v[0] = f2pk(vxl, vxh);
    v[1] = f2pk(vyl, vyh);
    v[2] = f2pk(vzl, vzh);
}

// Packed nearest rotation: lane-lo = pred matrix, lane-hi = target matrix.
__device__ __forceinline__ void nearest_rotation2(const ull M[9], ull R[9])
{
    // A = M^T M
    ull a00 = f2fma(M[0],M[0], f2fma(M[3],M[3], f2mul(M[6],M[6])));
    ull a11 = f2fma(M[1],M[1], f2fma(M[4],M[4], f2mul(M[7],M[7])));
    ull a22 = f2fma(M[2],M[2], f2fma(M[5],M[5], f2mul(M[8],M[8])));
    ull a01 = f2fma(M[0],M[1], f2fma(M[3],M[4], f2mul(M[6],M[7])));
    ull a02 = f2fma(M[0],M[2], f2fma(M[3],M[5], f2mul(M[6],M[8])));
    ull a12 = f2fma(M[1],M[2], f2fma(M[4],M[5], f2mul(M[7],M[8])));

    // Cardano
    ull q   = f2mul(f2add(f2add(a00,a11),a22), f2c(1.0f/3.0f));
    ull b00 = f2sub(a00,q), b11 = f2sub(a11,q), b22 = f2sub(a22,q);
    ull toff = f2fma(a01,a01, f2fma(a02,a02, f2mul(a12,a12)));
    ull p2  = f2fma(b00,b00, f2fma(b11,b11, f2fma(b22,b22, f2add(toff,toff))));
    ull p2s = f2fma(p2, f2c(1.0f/6.0f), f2c(1e-30f));
    ull ip  = f2rsqrt_clamped(p2s, 1e-38f);
    ull p   = f2mul(p2s, ip);

    ull t1 = f2cr(b11,b22, a12,a12);
    ull t2 = f2cr(a01,b22, a12,a02);
    ull t3 = f2cr(a01,a12, b11,a02);
    ull det = f2fma(a02,t3, f2fma(F2NEG(a01),t2, f2mul(b00,t1)));
    ull rr = f2mul(f2mul(det, f2mul(f2mul(ip,ip), ip)), f2c(0.5f));

    float rl, rh; f2up(rr, rl, rh);
    rl = fminf(1.f, fmaxf(-1.f, rl));
    rh = fminf(1.f, fmaxf(-1.f, rh));
    float phl = fast_acos(rl) * (1.0f/3.0f);
    float phh = fast_acos(rh) * (1.0f/3.0f);
    float sl, cl, sh, chh;
    __sincosf(phl, &sl, &cl);
    __sincosf(phh, &sh, &chh);
    ull s2 = f2pk(sl, sh), c2 = f2pk(cl, chh);

    ull lam1 = f2fma(p, f2add(c2,c2), q);
    ull lam3 = f2fma(F2NEG(p), f2fma(s2, f2c(1.7320508075688772f), c2), q);
    ull lam2 = f2sub(f2sub(f2add(f2add(q,q),q), lam1), lam3);

    ull v1[3], v3[3];
    eigvec2(a00,a01,a02,a11,a12,a22, lam1, v1);
    eigvec2(a00,a01,a02,a11,a12,a22, lam3, v3);

    // v2 = v3 x v1
    ull v2x = f2cr(v3[1],v1[2], v3[2],v1[1]);
    ull v2y = f2cr(v3[2],v1[0], v3[0],v1[2]);
    ull v2z = f2cr(v3[0],v1[1], v3[1],v1[0]);

    ull is1 = f2rsqrt_clamped(lam1, 1e-30f);
    ull is2 = f2rsqrt_clamped(lam2, 1e-30f);

    ull u1x = f2mul(f2fma(M[0],v1[0], f2fma(M[1],v1[1], f2mul(M[2],v1[2]))), is1);
    ull u1y = f2mul(f2fma(M[3],v1[0], f2fma(M[4],v1[1], f2mul(M[5],v1[2]))), is1);
    ull u1z = f2mul(f2fma(M[6],v1[0], f2fma(M[7],v1[1], f2mul(M[8],v1[2]))), is1);

    ull u2x = f2mul(f2fma(M[0],v2x, f2fma(M[1],v2y, f2mul(M[2],v2z))), is2);
    ull u2y = f2mul(f2fma(M[3],v2x, f2fma(M[4],v2y, f2mul(M[5],v2z))), is2);
    ull u2z = f2mul(f2fma(M[6],v2x, f2fma(M[7],v2y, f2mul(M[8],v2z))), is2);

    // u3 = u1 x u2 (encodes the SVD det-correction)
    ull u3x = f2cr(u1y,u2z, u1z,u2y);
    ull u3y = f2cr(u1z,u2x, u1x,u2z);
    ull u3z = f2cr(u1x,u2y, u1y,u2x);

    // R = u1 v1^T + u2 v2^T + u3 v3^T
    R[0] = f2fma(u1x,v1[0], f2fma(u2x,v2x, f2mul(u3x,v3[0])));
    R[1] = f2fma(u1x,v1[1], f2fma(u2x,v2y, f2mul(u3x,v3[1])));
    R[2] = f2fma(u1x,v1[2], f2fma(u2x,v2z, f2mul(u3x,v3[2])));
    R[3] = f2fma(u1y,v1[0], f2fma(u2y,v2x, f2mul(u3y,v3[0])));
    R[4] = f2fma(u1y,v1[1], f2fma(u2y,v2y, f2mul(u3y,v3[1])));
    R[5] = f2fma(u1y,v1[2], f2fma(u2y,v2z, f2mul(u3y,v3[2])));
    R[6] = f2fma(u1z,v1[0], f2fma(u2z,v2x, f2mul(u3z,v3[0])));
    R[7] = f2fma(u1z,v1[1], f2fma(u2z,v2y, f2mul(u3z,v3[1])));
    R[8] = f2fma(u1z,v1[2], f2fma(u2z,v2z, f2mul(u3z,v3[2])));
}

__global__ void __launch_bounds__(TPB, 4)
rotloss_kernel(const float* __restrict__ pred, const float* __restrict__ target,
               float* __restrict__ out, int B, float invB)
{
    __shared__ float sp[TPB*9];
    __shared__ float st_[TPB*9];

    float trs = 0.f, ang = 0.f;

    int ibase = blockIdx.x * TPB;
    if (ibase < B) {
        int nitems = min(TPB, B - ibase);
        int nflt   = nitems * 9;
        long fbase = (long)ibase * 9;

        if (nitems == TPB) {
            const float4* p4 = (const float4*)(pred + fbase);
            const float4* t4 = (const float4*)(target + fbase);
            #pragma unroll
            for (int j = threadIdx.x; j < (TPB*9)/4; j += TPB) {
                ((float4*)sp)[j]  = p4[j];
                ((float4*)st_)[j] = t4[j];
            }
        } else {
            for (int j = threadIdx.x; j < nflt; j += TPB) {
                sp[j]  = pred[fbase + j];
                st_[j] = target[fbase + j];
            }
        }
        __syncthreads();

        if (threadIdx.x < nitems) {
            ull PT[9], R[9];
            #pragma unroll
            for (int k = 0; k < 9; k++)
                PT[k] = f2pk(sp[9*threadIdx.x + k], st_[9*threadIdx.x + k]);

            nearest_rotation2(PT, R);

            float tr = 0.f;
            #pragma unroll
            for (int k = 0; k < 9; k++) {
                float rp, rt; f2up(R[k], rp, rt);
                tr = fmaf(rp, rt, tr);
            }
            trs = tr;
            float ct = (tr - 1.0f) * 0.5f;
            ct = fminf(1.0f - 1e-7f, fmaxf(-1.0f + 1e-7f, ct));
            ang = fast_acos(ct) * RAD2DEG;
        }
    }

    // block reduction
    #pragma unroll
    for (int off = 16; off; off >>= 1) {
        trs += __shfl_down_sync(0xffffffffu, trs, off);
        ang += __shfl_down_sync(0xffffffffu, ang, off);
    }
    __shared__ float str[TPB/32], sang[TPB/32];
    int w = threadIdx.x >> 5, l = threadIdx.x & 31;
    if (l == 0) { str[w] = trs; sang[w] = ang; }
    __syncthreads();
    if (threadIdx.x == 0) {
        float t2 = 0.f, a2 = 0.f;
        #pragma unroll
        for (int j = 0; j < TPB/32; j++) { t2 += str[j]; a2 += sang[j]; }
        g_ptr_[blockIdx.x] = t2;
        g_pang[blockIdx.x] = a2;
    }

    // last-block finalize (self-resetting counter -> graph-replay safe)
    __threadfence();
    __shared__ bool isLast;
    if (threadIdx.x == 0) {
        unsigned int t = atomicAdd(&g_count, 1u);
        isLast = (t == gridDim.x - 1);
    }
    __syncthreads();
    if (!isLast) return;

    float t2 = 0.f, a2 = 0.f;
    for (int j = threadIdx.x; j < (int)gridDim.x; j += TPB) {
        t2 += g_ptr_[j];
        a2 += g_pang[j];
    }
    #pragma unroll
    for (int off = 16; off; off >>= 1) {
        t2 += __shfl_down_sync(0xffffffffu, t2, off);
        a2 += __shfl_down_sync(0xffffffffu, a2, off);
    }
    __shared__ float ftr[TPB/32], fang[TPB/32];
    if (l == 0) { ftr[w] = t2; fang[w] = a2; }
    __syncthreads();
    if (threadIdx.x == 0) {
        float tt = 0.f, aa = 0.f;
        #pragma unroll
        for (int j = 0; j < TPB/32; j++) { tt += ftr[j]; aa += fang[j]; }
        out[0] = fmaf(-2.0f * invB, tt, 6.0f) + ANGW * aa * invB;
        g_count = 0;
    }
}

extern "C" void kernel_launch(void* const* d_in, const int* in_sizes, int n_in,
                              void* d_out, int out_size)
{
    const float* pred   = (const float*)d_in[0];
    const float* target = (const float*)d_in[1];
    float* out = (float*)d_out;

    int B = in_sizes[0] / 9;
    int blocks = (B + TPB - 1) / TPB;
    if (blocks > MAX_BLOCKS) blocks = MAX_BLOCKS;
    if (blocks < 1) blocks = 1;

    rotloss_kernel<<<blocks, TPB>>>(pred, target, out, B, 1.0f / (float)B);
}